// round 14
// baseline (speedup 1.0000x reference)
#include <cuda_runtime.h>
#include <cuda_bf16.h>
#include <cstdint>

#define IN_F   4096
#define OUT_F  4096
#define NTOK   16384
#define BW     8
#define KW     17          // 2*BW+1
#define NO     4           // outputs per thread
#define NP     9           // packed weight pairs per output
#define WARPS  8           // warps per block (256 threads)
#define GY     256         // token stride / grid.y -> 64 tokens per block
#define BWIN_F 1040        // block window floats: 1024 outputs + 2*BW halo
#define BWIN4  260         // float4 chunks per block window
#define BUF_B  (BWIN4 * 16)            // 4160 bytes per buffer
#define NBUF   12
#define PDIST  8           // pending groups after wait (tokens in flight)
#define BROWS  (WARPS * 32 * NO)           // 1024 band rows per block
#define WST_F  (BROWS * KW)                // 17408 staged weight floats
#define PIPE_B (NBUF * BUF_B)              // 49920 B
#define WST_B  (WST_F * 4)                 // 69632 B
#define SMEM_B (WST_B > PIPE_B ? WST_B : PIPE_B)   // 69632 B

__device__ __forceinline__ void cp16(uint32_t dst_smem, const float* src) {
    asm volatile("cp.async.cg.shared.global [%0], [%1], 16;\n"
                 :: "r"(dst_smem), "l"(src) : "memory");
}
__device__ __forceinline__ void cp4(uint32_t dst_smem, const float* src) {
    asm volatile("cp.async.ca.shared.global [%0], [%1], 4;\n"
                 :: "r"(dst_smem), "l"(src) : "memory");
}
__device__ __forceinline__ void cp_commit() {
    asm volatile("cp.async.commit_group;\n" ::: "memory");
}

// ---- packed f32x2 helpers (sm_103a) ----
__device__ __forceinline__ uint64_t pk2(float lo, float hi) {
    uint64_t r;
    asm("mov.b64 %0, {%1, %2};" : "=l"(r) : "f"(lo), "f"(hi));
    return r;
}
__device__ __forceinline__ void fma2(uint64_t& d, uint64_t a, uint64_t b) {
    asm("fma.rn.f32x2 %0, %1, %2, %0;" : "+l"(d) : "l"(a), "l"(b));
}
__device__ __forceinline__ void upk2(float& lo, float& hi, uint64_t v) {
    asm("mov.b64 {%0, %1}, %2;" : "=f"(lo), "=f"(hi) : "l"(v));
}

// block covers 1024 consecutive outputs (grid.x = 4); one shared window/token.
__global__ __launch_bounds__(256, 2) void band_linear_kernel(
    const float* __restrict__ x,
    const float* __restrict__ w,
    const float* __restrict__ bias,
    float* __restrict__ out)
{
    extern __shared__ char dsm[];
    float* smw = reinterpret_cast<float*>(dsm);   // weight stage (recycled into pipeline)

    const int tid  = threadIdx.x;
    const int warp = tid >> 5;
    const int lane = tid & 31;
    const int B      = blockIdx.x * BROWS;        // block's first output
    const int o_base = B + warp * 128 + lane * NO;

    // ---- async coalesced weight staging: 1024 rows x 17 taps, one group ----
    {
        const uint32_t smw_a = (uint32_t)__cvta_generic_to_shared(smw);
#pragma unroll
        for (int i = 0; i < WST_F / 256; ++i) {              // 68 cp.async each
            const int e = tid + i * 256;
            const int r = e / KW;
            const int k = e - r * KW;
            const int o = B + r;
            int col = o - BW + k;
            col = col < 0 ? 0 : (col >= IN_F ? IN_F - 1 : col);  // clamp; zeroed later
            cp4(smw_a + (uint32_t)(e * 4), w + (long)o * IN_F + col);
        }
        cp_commit();
    }
    asm volatile("cp.async.wait_group 0;\n" ::: "memory");
    __syncthreads();

    // ---- build PACKED tap-pair weights in registers; smem recycled after ----
    uint64_t wpk[NO][NP];
    uint64_t bp[NO];
    {
        const int rloc = warp * 128 + lane * NO;
#pragma unroll
        for (int oo = 0; oo < NO; ++oo) {
            const int o = o_base + oo;
            bp[oo] = pk2(bias[o], 0.0f);
            const int ms = oo >> 1;
#pragma unroll
            for (int m = 0; m < NP; ++m) {
                const int am  = ms + m;
                const int klo = 2 * am - oo;
                const int khi = klo + 1;
                float vlo = 0.0f, vhi = 0.0f;
                if (klo >= 0 && klo < KW) {
                    const int col = o - BW + klo;
                    const float v = smw[(rloc + oo) * KW + klo];
                    vlo = (col >= 0 && col < IN_F) ? v : 0.0f;
                }
                if (khi >= 0 && khi < KW) {
                    const int col = o - BW + khi;
                    const float v = smw[(rloc + oo) * KW + khi];
                    vhi = (col >= 0 && col < IN_F) ? v : 0.0f;
                }
                wpk[oo][m] = pk2(vlo, vhi);
            }
        }
    }
    __syncthreads();   // all reads of smw done before pipeline overwrites it

    // ---- block-window staging: 260 chunks over 256 threads ----
    const int W0 = B - BW;                 // window start col (multiple of 4)
    int sm_ = W0 + 4 * tid;                // main chunk source
    sm_ = sm_ < 0 ? 0 : (sm_ > IN_F - 4 ? IN_F - 4 : sm_);
    const bool extra = (tid < BWIN4 - 256);          // tids 0..3 take chunks 256..259
    int se_ = W0 + 4 * (256 + tid);
    se_ = se_ < 0 ? 0 : (se_ > IN_F - 4 ? IN_F - 4 : se_);
    // clamped chunks pair only with zero weights -> harmless.

    const uint32_t pipe = (uint32_t)__cvta_generic_to_shared(dsm);
    const uint32_t offm = (uint32_t)(tid * 16);
    const uint32_t offe = (uint32_t)((256 + tid) * 16);

    const int n0 = blockIdx.y;

    // stage one token's block window into buffer bi (1 group per thread)
    auto stage_tok = [&](int tok, int bi) {
        const float* xrow = x + (long)tok * IN_F;
        const uint32_t b = pipe + (uint32_t)(bi * BUF_B);
        cp16(b + offm, xrow + sm_);
        if (extra) cp16(b + offe, xrow + se_);
    };

    // ---- prologue: stage tokens n0 .. n0+7*GY into buffers 0..7 ----
#pragma unroll
    for (int p = 0; p < PDIST; ++p) {
        stage_tok(n0 + p * GY, p);   // always < NTOK (n0<256, 8*256+255<16384)
        cp_commit();
    }

    int buf  = 0;
    int pbuf = PDIST;
    for (int n = n0; n < NTOK; n += 2 * GY) {
        // ---- stage tokens n+8*GY, n+9*GY (guarded; empty groups are legal) ----
        {
            const int pnA = n + PDIST * GY;
            if (pnA < NTOK) stage_tok(pnA, pbuf);
            cp_commit();
            const int pnB = n + (PDIST + 1) * GY;
            if (pnB < NTOK) stage_tok(pnB, pbuf + 1 == NBUF ? 0 : pbuf + 1);
            cp_commit();
        }

        // ---- own groups <= PDIST pending, then publish block-wide ----
        asm volatile("cp.async.wait_group %0;\n" :: "n"(PDIST) : "memory");
        __syncthreads();

#pragma unroll
        for (int t = 0; t < 2; ++t) {
            const int nt = n + t * GY;     // always < NTOK (64 tokens, 32 iters exactly)
            const int bb = (buf + t == NBUF) ? 0 : buf + t;
            const char* swp = dsm + (size_t)bb * BUF_B;

            // window as 10 native 64-bit pairs: 5 conflict-free LDS.128
            const size_t base = (size_t)(warp * 128 + lane * NO) * 4;
            uint64_t xq[10];
#pragma unroll
            for (int c = 0; c < 5; ++c) {
                const ulonglong2 v = *reinterpret_cast<const ulonglong2*>(
                    swp + base + (size_t)c * 16);
                xq[2 * c]     = v.x;
                xq[2 * c + 1] = v.y;
            }

            uint64_t acc[NO];
#pragma unroll
            for (int oo = 0; oo < NO; ++oo) {
                acc[oo] = bp[oo];
                const int ms = oo >> 1;
#pragma unroll
                for (int m = 0; m < NP; ++m)
                    fma2(acc[oo], xq[ms + m], wpk[oo][m]);
            }

            float4 o4;
            {
                float lo, hi;
                upk2(lo, hi, acc[0]); o4.x = lo + hi;
                upk2(lo, hi, acc[1]); o4.y = lo + hi;
                upk2(lo, hi, acc[2]); o4.z = lo + hi;
                upk2(lo, hi, acc[3]); o4.w = lo + hi;
            }
            *reinterpret_cast<float4*>(out + (long)nt * OUT_F + o_base) = o4;
        }

        buf  = (buf  + 2 >= NBUF) ? buf  + 2 - NBUF : buf  + 2;
        pbuf = (pbuf + 2 >= NBUF) ? pbuf + 2 - NBUF : pbuf + 2;
    }
}

extern "C" void kernel_launch(void* const* d_in, const int* in_sizes, int n_in,
                              void* d_out, int out_size)
{
    const float* x    = (const float*)d_in[0];   // [NTOK, IN_F]
    const float* w    = (const float*)d_in[1];   // [OUT_F, IN_F]
    const float* bias = (const float*)d_in[2];   // [OUT_F]
    float* out = (float*)d_out;

    cudaFuncSetAttribute(band_linear_kernel,
                         cudaFuncAttributeMaxDynamicSharedMemorySize, SMEM_B);

    dim3 grid(OUT_F / BROWS, GY);                // (4, 256)
    dim3 block(WARPS * 32);                      // 256
    band_linear_kernel<<<grid, block, SMEM_B>>>(x, w, bias, out);
}

// round 16
// speedup vs baseline: 1.1722x; 1.1722x over previous
#include <cuda_runtime.h>
#include <cuda_bf16.h>
#include <cstdint>

#define IN_F   4096
#define OUT_F  4096
#define NTOK   16384
#define BW     8
#define KW     17          // 2*BW+1
#define NO     4           // outputs per thread
#define NP     9           // packed weight pairs per output
#define WARPS  8           // warps per block (256 threads)
#define GY     256         // token stride / grid.y -> 64 tokens per block
#define WIN_B  576         // 144 floats per warp window
#define TBUF_B 640         // token buffer: 32B guard + 576B data + 32B guard
#define NSLOT  8           // pair slots per warp
#define SLOT_B (2*TBUF_B)  // 1280
#define WPIPE_B (NSLOT*SLOT_B)        // 10240 B per warp
#define PIPE_B  (WARPS*WPIPE_B)       // 81920 B
#define MBAR_OFF PIPE_B               // mbarriers after pipe (outside weight union)
#define NPAIR_IT 32        // 32 pairs = 64 tokens per block
#define PDP    6           // pairs prefetched ahead
#define BROWS  (WARPS * 32 * NO)      // 1024 band rows per block
#define WST_F  (BROWS * KW)           // 17408 staged weight floats (69632 B < PIPE_B)
#define SMEM_B (MBAR_OFF + WARPS*NSLOT*8)   // 82432 B

__device__ __forceinline__ void cp4(uint32_t dst_smem, const float* src) {
    asm volatile("cp.async.ca.shared.global [%0], [%1], 4;\n"
                 :: "r"(dst_smem), "l"(src) : "memory");
}
__device__ __forceinline__ void bulk576(uint32_t dst_smem, const float* src, uint32_t mbar) {
    asm volatile("cp.async.bulk.shared::cta.global.mbarrier::complete_tx::bytes "
                 "[%0], [%1], %2, [%3];\n"
                 :: "r"(dst_smem), "l"(src), "r"(576u), "r"(mbar) : "memory");
}
__device__ __forceinline__ void mbar_expect(uint32_t mbar, uint32_t bytes) {
    asm volatile("mbarrier.arrive.expect_tx.shared.b64 _, [%0], %1;\n"
                 :: "r"(mbar), "r"(bytes) : "memory");
}
__device__ __forceinline__ void mbar_wait(uint32_t mbar, uint32_t parity) {
    asm volatile(
        "{\n\t.reg .pred P1;\n\t"
        "WAIT_LOOP_%=:\n\t"
        "mbarrier.try_wait.parity.acquire.cta.shared::cta.b64 P1, [%0], %1, 0x989680;\n\t"
        "@P1 bra.uni WAIT_DONE_%=;\n\t"
        "bra.uni WAIT_LOOP_%=;\n\t"
        "WAIT_DONE_%=:\n\t}"
        :: "r"(mbar), "r"(parity) : "memory");
}

// ---- packed f32x2 helpers (sm_103a) ----
__device__ __forceinline__ uint64_t pk2(float lo, float hi) {
    uint64_t r;
    asm("mov.b64 %0, {%1, %2};" : "=l"(r) : "f"(lo), "f"(hi));
    return r;
}
__device__ __forceinline__ void fma2(uint64_t& d, uint64_t a, uint64_t b) {
    asm("fma.rn.f32x2 %0, %1, %2, %0;" : "+l"(d) : "l"(a), "l"(b));
}
__device__ __forceinline__ void upk2(float& lo, float& hi, uint64_t v) {
    asm("mov.b64 {%0, %1}, %2;" : "=f"(lo), "=f"(hi) : "l"(v));
}

// warp covers 128 consecutive outputs; block covers 1024; grid.x = 4.
__global__ __launch_bounds__(256, 2) void band_linear_kernel(
    const float* __restrict__ x,
    const float* __restrict__ w,
    const float* __restrict__ bias,
    float* __restrict__ out)
{
    extern __shared__ char dsm[];
    float* smw = reinterpret_cast<float*>(dsm);   // weight stage (recycled into pipe)

    const int tid  = threadIdx.x;
    const int warp = tid >> 5;
    const int lane = tid & 31;
    const int wbase  = (blockIdx.x * WARPS + warp) * 128;
    const int o_base = wbase + lane * NO;
    const int win0   = wbase - BW;                // multiple of 4

    const uint32_t smem0   = (uint32_t)__cvta_generic_to_shared(dsm);
    const uint32_t mbar_b  = smem0 + MBAR_OFF + (uint32_t)(warp * NSLOT * 8);
    const uint32_t wpipe   = smem0 + (uint32_t)(warp * WPIPE_B);

    // ---- init this warp's 8 mbarriers (count=1), visible to async proxy ----
    if (lane == 0) {
#pragma unroll
        for (int s = 0; s < NSLOT; ++s)
            asm volatile("mbarrier.init.shared.b64 [%0], 1;\n"
                         :: "r"(mbar_b + (uint32_t)(s * 8)) : "memory");
        asm volatile("fence.proxy.async.shared::cta;\n" ::: "memory");
    }
    __syncwarp();

    // ---- async coalesced weight staging: 1024 rows x 17 taps, one group ----
    {
        const int row0 = blockIdx.x * BROWS;
#pragma unroll
        for (int i = 0; i < WST_F / 256; ++i) {              // 68 cp.async each
            const int e = tid + i * 256;
            const int r = e / KW;
            const int k = e - r * KW;
            const int o = row0 + r;
            int col = o - BW + k;
            col = col < 0 ? 0 : (col >= IN_F ? IN_F - 1 : col);  // clamp; zeroed later
            cp4(smem0 + (uint32_t)(e * 4), w + (long)o * IN_F + col);
        }
        asm volatile("cp.async.commit_group;\ncp.async.wait_group 0;\n" ::: "memory");
    }
    __syncthreads();

    // ---- build PACKED tap-pair weights in registers; smem recycled after ----
    uint64_t wpk[NO][NP];
    uint64_t bp[NO];
    {
        const int rloc = warp * 128 + lane * NO;
#pragma unroll
        for (int oo = 0; oo < NO; ++oo) {
            const int o = o_base + oo;
            bp[oo] = pk2(bias[o], 0.0f);
            const int ms = oo >> 1;
#pragma unroll
            for (int m = 0; m < NP; ++m) {
                const int am  = ms + m;
                const int klo = 2 * am - oo;
                const int khi = klo + 1;
                float vlo = 0.0f, vhi = 0.0f;
                if (klo >= 0 && klo < KW) {
                    const int col = o - BW + klo;
                    const float v = smw[(rloc + oo) * KW + klo];
                    vlo = (col >= 0 && col < IN_F) ? v : 0.0f;
                }
                if (khi >= 0 && khi < KW) {
                    const int col = o - BW + khi;
                    const float v = smw[(rloc + oo) * KW + khi];
                    vhi = (col >= 0 && col < IN_F) ? v : 0.0f;
                }
                wpk[oo][m] = pk2(vlo, vhi);
            }
        }
    }
    __syncthreads();   // all reads of smw done before pipe writes overwrite it

    // ---- zero guard bytes of this warp's 16 token buffers ----
    // Bulk copies write only [32,608) of each buffer; clamped-window warps read
    // up to 32B into a guard and rely on guard*0 == 0 -> guards must be finite.
    {
        char* wp0 = dsm + (size_t)warp * WPIPE_B;
        if (lane < 2 * NSLOT) {          // one token buffer per lane (16 lanes)
            float4 z = make_float4(0.f, 0.f, 0.f, 0.f);
            char* tb = wp0 + (size_t)lane * TBUF_B;
            *reinterpret_cast<float4*>(tb)       = z;
            *reinterpret_cast<float4*>(tb + 16)  = z;
            *reinterpret_cast<float4*>(tb + 608) = z;
            *reinterpret_cast<float4*>(tb + 624) = z;
        }
        __syncwarp();
    }

    // ---- bulk source: clamped window start; consumer compensates via base ----
    int sc = win0;
    sc = sc < 0 ? 0 : (sc > IN_F - 144 ? IN_F - 144 : sc);
    const int dlt   = sc - win0;            // 0, +8 (first warp), -8 (last warp)
    const int cbase = 32 - 4 * dlt;         // consumer byte base inside token buffer

    const int n0 = blockIdx.y;
    const float* xs = x + sc;               // source column base

    // issue both bulk copies of pair p into slot p&7 (lane 0 only)
    auto issue_pair = [&](int p) {
        if (lane == 0) {
            const int sl = p & (NSLOT - 1);
            const uint32_t mb = mbar_b + (uint32_t)(sl * 8);
            mbar_expect(mb, 2 * WIN_B);
            const uint32_t d0 = wpipe + (uint32_t)(sl * SLOT_B) + 32;
            bulk576(d0,          xs + (long)(n0 + (2 * p) * GY) * IN_F,     mb);
            bulk576(d0 + TBUF_B, xs + (long)(n0 + (2 * p + 1) * GY) * IN_F, mb);
        }
    };

    // ---- prologue: pairs 0..5 into slots 0..5 ----
#pragma unroll
    for (int p = 0; p < PDP; ++p) issue_pair(p);

    const char* wpc = dsm + (size_t)warp * WPIPE_B;

    for (int i = 0; i < NPAIR_IT; ++i) {
        // prefetch pair i+6 (slot reuse distance = 2 iterations)
        const int pp = i + PDP;
        if (pp < NPAIR_IT) issue_pair(pp);

        // wait for pair i (slot i&7, phase (i>>3)&1); acquire orders the LDS below
        mbar_wait(mbar_b + (uint32_t)((i & (NSLOT - 1)) * 8), (i >> 3) & 1);

        const char* slot = wpc + (size_t)(i & (NSLOT - 1)) * SLOT_B;

#pragma unroll
        for (int t = 0; t < 2; ++t) {
            const int nt = n0 + (2 * i + t) * GY;
            const char* swp = slot + (size_t)t * TBUF_B;

            // window as 10 native 64-bit pairs: 5 conflict-free LDS.128
            uint64_t xq[10];
#pragma unroll
            for (int c = 0; c < 5; ++c) {
                const ulonglong2 v = *reinterpret_cast<const ulonglong2*>(
                    swp + cbase + (size_t)(lane * NO + 4 * c) * 4);
                xq[2 * c]     = v.x;
                xq[2 * c + 1] = v.y;
            }

            uint64_t acc[NO];
#pragma unroll
            for (int oo = 0; oo < NO; ++oo) {
                acc[oo] = bp[oo];
                const int ms = oo >> 1;
#pragma unroll
                for (int m = 0; m < NP; ++m)
                    fma2(acc[oo], xq[ms + m], wpk[oo][m]);
            }

            float4 o4;
            {
                float lo, hi;
                upk2(lo, hi, acc[0]); o4.x = lo + hi;
                upk2(lo, hi, acc[1]); o4.y = lo + hi;
                upk2(lo, hi, acc[2]); o4.z = lo + hi;
                upk2(lo, hi, acc[3]); o4.w = lo + hi;
            }
            *reinterpret_cast<float4*>(out + (long)nt * OUT_F + o_base) = o4;
        }
    }
}

extern "C" void kernel_launch(void* const* d_in, const int* in_sizes, int n_in,
                              void* d_out, int out_size)
{
    const float* x    = (const float*)d_in[0];   // [NTOK, IN_F]
    const float* w    = (const float*)d_in[1];   // [OUT_F, IN_F]
    const float* bias = (const float*)d_in[2];   // [OUT_F]
    float* out = (float*)d_out;

    cudaFuncSetAttribute(band_linear_kernel,
                         cudaFuncAttributeMaxDynamicSharedMemorySize, SMEM_B);

    dim3 grid(OUT_F / BROWS, GY);                // (4, 256)
    dim3 block(WARPS * 32);                      // 256
    band_linear_kernel<<<grid, block, SMEM_B>>>(x, w, bias, out);
}